// round 14
// baseline (speedup 1.0000x reference)
#include <cuda_runtime.h>
#include <cuda_fp16.h>
#include <cstdint>

// ---------------- problem constants ----------------
#define B_   2
#define S_   2048
#define DIM_ 2048
#define NH_  32
#define NKV_ 8
#define HD_  64
#define QKVN 3072
#define M_   (B_ * S_)
#define KDIM 2048

// ---------------- scratch (fp16) ----------------
__device__ __half g_x_hi[(size_t)M_ * DIM_];
__device__ __half g_x_lo[(size_t)M_ * DIM_];
__device__ __half g_wqkvT_hi[(size_t)QKVN * DIM_];
__device__ __half g_woT_hi[(size_t)DIM_ * DIM_];
__device__ __half g_att_hi[(size_t)M_ * DIM_];
__device__ __half g_q_hi[(size_t)B_ * NH_ * S_ * HD_];
__device__ __half g_k_hi[(size_t)B_ * NKV_ * S_ * HD_];
__device__ __half g_v_hi[(size_t)B_ * NKV_ * S_ * HD_];

// ============================================================================
// helpers (sm_80-compatible only)
// ============================================================================
__device__ __forceinline__ uint32_t smem_u32(const void* p) {
    uint32_t a;
    asm("{ .reg .u64 t; cvta.to.shared.u64 t, %1; cvt.u32.u64 %0, t; }"
        : "=r"(a) : "l"(p));
    return a;
}
__device__ __forceinline__ void cp_async16(uint32_t s, const void* g) {
    asm volatile("cp.async.cg.shared.global [%0], [%1], 16;" :: "r"(s), "l"(g));
}
__device__ __forceinline__ void cp_commit() {
    asm volatile("cp.async.commit_group;" ::: "memory");
}
__device__ __forceinline__ void cp_wait0() {
    asm volatile("cp.async.wait_group 0;" ::: "memory");
}
__device__ __forceinline__ void ldmatrix_x4(uint32_t& r0, uint32_t& r1,
                                            uint32_t& r2, uint32_t& r3, uint32_t a) {
    asm volatile("ldmatrix.sync.aligned.m8n8.x4.shared.b16 {%0,%1,%2,%3}, [%4];"
                 : "=r"(r0), "=r"(r1), "=r"(r2), "=r"(r3) : "r"(a));
}
__device__ __forceinline__ void ldmatrix_x4_trans(uint32_t& r0, uint32_t& r1,
                                                  uint32_t& r2, uint32_t& r3, uint32_t a) {
    asm volatile("ldmatrix.sync.aligned.m8n8.x4.trans.shared.b16 {%0,%1,%2,%3}, [%4];"
                 : "=r"(r0), "=r"(r1), "=r"(r2), "=r"(r3) : "r"(a));
}
__device__ __forceinline__ void mma_fp16(float* c, uint32_t a0, uint32_t a1,
                                         uint32_t a2, uint32_t a3,
                                         uint32_t b0, uint32_t b1) {
    asm volatile(
        "mma.sync.aligned.m16n8k16.row.col.f32.f16.f16.f32 "
        "{%0,%1,%2,%3}, {%4,%5,%6,%7}, {%8,%9}, {%0,%1,%2,%3};"
        : "+f"(c[0]), "+f"(c[1]), "+f"(c[2]), "+f"(c[3])
        : "r"(a0), "r"(a1), "r"(a2), "r"(a3), "r"(b0), "r"(b1));
}
__device__ __forceinline__ uint32_t pack_h2(float a, float b) {
    __half2 t = __floats2half2_rn(a, b);
    return *(uint32_t*)&t;
}

// ============================================================================
// GEMM tiling: 64 M-rows per CTA, BK=64 (32 iterations, 4 k-steps each)
// ============================================================================
#define GBM 64
#define GBN 128
#define GBK 64
#define GSTRIDE 144                   // 64 halves (128B) + 16B pad
#define GTILE_A (GBM * GSTRIDE)       // 9216 B
#define GTILE_B (GBN * GSTRIDE)       // 18432 B

// ---- tc_gemm2: C = (Ah+Al) @ Bh^T, fused rope + Q/K/V epilogue ----
#define G2STAGE (2 * GTILE_A + GTILE_B)   // 36864
#define G2SMEM (2 * G2STAGE)              // 73728

__global__ __launch_bounds__(128) void tc_gemm2_kernel(
    const __half* __restrict__ Ah, const __half* __restrict__ Al,
    const __half* __restrict__ Bh,
    const float* __restrict__ fc,
    __half* __restrict__ Qh,
    __half* __restrict__ Kh,
    __half* __restrict__ Vh,
    int N, int K)
{
    extern __shared__ char smem[];
    const uint32_t sb = smem_u32(smem);
    const int tid = threadIdx.x;
    const int wid = tid >> 5;
    const int lane = tid & 31;
    const int mb = blockIdx.y * GBM;
    const int nb = blockIdx.x * GBN;
    const int wm = (wid >> 1) * 32;    // warp tile 32x64
    const int wn = (wid & 1) * 64;

    auto load_stage = [&](int stage, int k0) {
        uint32_t base = sb + stage * G2STAGE;
        uint32_t sAh = base, sAl = base + GTILE_A, sB = base + 2 * GTILE_A;
#pragma unroll
        for (int i = 0; i < 4; i++) {
            int slot = i * 128 + tid;
            int r = slot >> 3, sg = slot & 7;
            cp_async16(sAh + r * GSTRIDE + sg * 16, Ah + (size_t)(mb + r) * K + k0 + sg * 8);
            cp_async16(sAl + r * GSTRIDE + sg * 16, Al + (size_t)(mb + r) * K + k0 + sg * 8);
        }
#pragma unroll
        for (int i = 0; i < 8; i++) {
            int slot = i * 128 + tid;
            int r = slot >> 3, sg = slot & 7;
            cp_async16(sB + r * GSTRIDE + sg * 16, Bh + (size_t)(nb + r) * K + k0 + sg * 8);
        }
        cp_commit();
    };

    float acc[2][8][4];
#pragma unroll
    for (int i = 0; i < 2; i++)
#pragma unroll
        for (int j = 0; j < 8; j++)
#pragma unroll
            for (int e = 0; e < 4; e++) acc[i][j][e] = 0.f;

    const uint32_t aoff = (uint32_t)((lane & 15) * GSTRIDE + (lane >> 4) * 16);
    const uint32_t boff = (uint32_t)(((lane & 7) + ((lane >> 4) * 8)) * GSTRIDE
                                     + (((lane >> 3) & 1) * 16));

    load_stage(0, 0);
    const int niter = K / GBK;
    for (int it = 0; it < niter; it++) {
        cp_wait0();
        __syncthreads();
        if (it + 1 < niter) load_stage((it + 1) & 1, (it + 1) * GBK);

        uint32_t base = sb + (it & 1) * G2STAGE;
        uint32_t bAh = base, bAl = base + GTILE_A, bB = base + 2 * GTILE_A;

#pragma unroll
        for (int ks = 0; ks < 4; ks++) {
            uint32_t kb = (uint32_t)(ks * 32);
            uint32_t ah[2][4], al[2][4];
#pragma unroll
            for (int mi = 0; mi < 2; mi++) {
                uint32_t rowb = (uint32_t)((wm + mi * 16) * GSTRIDE) + kb;
                ldmatrix_x4(ah[mi][0], ah[mi][1], ah[mi][2], ah[mi][3], bAh + rowb + aoff);
                ldmatrix_x4(al[mi][0], al[mi][1], al[mi][2], al[mi][3], bAl + rowb + aoff);
            }
            uint32_t bf[8][2];
#pragma unroll
            for (int nj = 0; nj < 4; nj++) {
                uint32_t rowb = (uint32_t)((wn + nj * 16) * GSTRIDE) + kb;
                uint32_t t0, t1, t2, t3;
                ldmatrix_x4(t0, t1, t2, t3, bB + rowb + boff);
                bf[nj * 2][0] = t0; bf[nj * 2][1] = t1;
                bf[nj * 2 + 1][0] = t2; bf[nj * 2 + 1][1] = t3;
            }
#pragma unroll
            for (int mi = 0; mi < 2; mi++)
#pragma unroll
                for (int nj = 0; nj < 8; nj++) {
                    mma_fp16(acc[mi][nj], ah[mi][0], ah[mi][1], ah[mi][2], ah[mi][3],
                             bf[nj][0], bf[nj][1]);
                    mma_fp16(acc[mi][nj], al[mi][0], al[mi][1], al[mi][2], al[mi][3],
                             bf[nj][0], bf[nj][1]);
                }
        }
        // trailing __syncthreads removed: next-iter top barrier provides ordering
    }

    const int g = lane >> 2, c = lane & 3;
#pragma unroll
    for (int mi = 0; mi < 2; mi++) {
#pragma unroll
        for (int nj = 0; nj < 8; nj++) {
            const int col = nb + wn + nj * 8 + 2 * c;
#pragma unroll
            for (int rr = 0; rr < 2; rr++) {
                const int row = mb + wm + mi * 16 + g + rr * 8;
                float v0 = acc[mi][nj][rr * 2 + 0];
                float v1 = acc[mi][nj][rr * 2 + 1];
                const int b = row >> 11, s = row & (S_ - 1);
                const int d = col & 63;
                if (col < DIM_ + NKV_ * HD_) {
                    float2 f = *(const float2*)(fc + (size_t)s * HD_ + d);
                    float rx = v0 * f.x - v1 * f.y;
                    float ry = v1 * f.x + v0 * f.y;
                    v0 = rx; v1 = ry;
                }
                if (col < DIM_) {
                    int h = col >> 6;
                    size_t o = ((size_t)(b * NH_ + h) * S_ + s) * HD_ + d;
                    *(uint32_t*)(Qh + o) = pack_h2(v0, v1);
                } else if (col < DIM_ + NKV_ * HD_) {
                    int kvh = (col - DIM_) >> 6;
                    size_t o = ((size_t)(b * NKV_ + kvh) * S_ + s) * HD_ + d;
                    *(uint32_t*)(Kh + o) = pack_h2(v0, v1);
                } else {
                    int kvh = (col - DIM_ - NKV_ * HD_) >> 6;
                    size_t o = ((size_t)(b * NKV_ + kvh) * S_ + s) * HD_ + d;
                    *(uint32_t*)(Vh + o) = pack_h2(v0, v1);
                }
            }
        }
    }
}

// ---- tc_gemm1: single-term fp16 GEMM (out = att @ woT^T), BK=64 ----
#define G1STAGE (GTILE_A + GTILE_B)   // 27648
#define G1SMEM (2 * G1STAGE)          // 55296

__global__ __launch_bounds__(128) void tc_gemm1_kernel(
    const __half* __restrict__ A, const __half* __restrict__ B,
    float* __restrict__ C, int N, int K)
{
    extern __shared__ char smem[];
    const uint32_t sb = smem_u32(smem);
    const int tid = threadIdx.x;
    const int wid = tid >> 5;
    const int lane = tid & 31;
    const int mb = blockIdx.y * GBM;
    const int nb = blockIdx.x * GBN;
    const int wm = (wid >> 1) * 32;
    const int wn = (wid & 1) * 64;

    auto load_stage = [&](int stage, int k0) {
        uint32_t base = sb + stage * G1STAGE;
        uint32_t sA = base, sB = base + GTILE_A;
#pragma unroll
        for (int i = 0; i < 4; i++) {
            int slot = i * 128 + tid;
            int r = slot >> 3, sg = slot & 7;
            cp_async16(sA + r * GSTRIDE + sg * 16, A + (size_t)(mb + r) * K + k0 + sg * 8);
        }
#pragma unroll
        for (int i = 0; i < 8; i++) {
            int slot = i * 128 + tid;
            int r = slot >> 3, sg = slot & 7;
            cp_async16(sB + r * GSTRIDE + sg * 16, B + (size_t)(nb + r) * K + k0 + sg * 8);
        }
        cp_commit();
    };

    float acc[2][8][4];
#pragma unroll
    for (int i = 0; i < 2; i++)
#pragma unroll
        for (int j = 0; j < 8; j++)
#pragma unroll
            for (int e = 0; e < 4; e++) acc[i][j][e] = 0.f;

    const uint32_t aoff = (uint32_t)((lane & 15) * GSTRIDE + (lane >> 4) * 16);
    const uint32_t boff = (uint32_t)(((lane & 7) + ((lane >> 4) * 8)) * GSTRIDE
                                     + (((lane >> 3) & 1) * 16));

    load_stage(0, 0);
    const int niter = K / GBK;
    for (int it = 0; it < niter; it++) {
        cp_wait0();
        __syncthreads();
        if (it + 1 < niter) load_stage((it + 1) & 1, (it + 1) * GBK);

        uint32_t base = sb + (it & 1) * G1STAGE;
        uint32_t bA = base, bB = base + GTILE_A;

#pragma unroll
        for (int ks = 0; ks < 4; ks++) {
            uint32_t kb = (uint32_t)(ks * 32);
            uint32_t af[2][4];
#pragma unroll
            for (int mi = 0; mi < 2; mi++) {
                uint32_t rowb = (uint32_t)((wm + mi * 16) * GSTRIDE) + kb;
                ldmatrix_x4(af[mi][0], af[mi][1], af[mi][2], af[mi][3], bA + rowb + aoff);
            }
            uint32_t bf[8][2];
#pragma unroll
            for (int nj = 0; nj < 4; nj++) {
                uint32_t rowb = (uint32_t)((wn + nj * 16) * GSTRIDE) + kb;
                uint32_t t0, t1, t2, t3;
                ldmatrix_x4(t0, t1, t2, t3, bB + rowb + boff);
                bf[nj * 2][0] = t0; bf[nj * 2][1] = t1;
                bf[nj * 2 + 1][0] = t2; bf[nj * 2 + 1][1] = t3;
            }
#pragma unroll
            for (int mi = 0; mi < 2; mi++)
#pragma unroll
                for (int nj = 0; nj < 8; nj++)
                    mma_fp16(acc[mi][nj], af[mi][0], af[mi][1], af[mi][2], af[mi][3],
                             bf[nj][0], bf[nj][1]);
        }
        // trailing __syncthreads removed
    }

    const int g = lane >> 2, c = lane & 3;
#pragma unroll
    for (int mi = 0; mi < 2; mi++) {
#pragma unroll
        for (int nj = 0; nj < 8; nj++) {
            float* cp0 = C + (size_t)(mb + wm + mi * 16 + g) * N + nb + wn + nj * 8 + 2 * c;
            float* cp1 = cp0 + (size_t)8 * N;
            *(float2*)cp0 = make_float2(acc[mi][nj][0], acc[mi][nj][1]);
            *(float2*)cp1 = make_float2(acc[mi][nj][2], acc[mi][nj][3]);
        }
    }
}

// ============================================================================
// Fused conversion kernel (unchanged)
// ============================================================================
#define NB_A (M_ * DIM_ / 4 / 256)            // 8192
#define NB_B ((KDIM / 32) * (QKVN / 32))      // 6144
#define NB_C ((KDIM / 32) * (DIM_ / 32))      // 4096
#define NB_TOTAL (NB_A + NB_B + NB_C)         // 18432

__global__ __launch_bounds__(256) void conv_fused_kernel(
    const float* __restrict__ x, __half* __restrict__ Xh, __half* __restrict__ Xl,
    const float* __restrict__ wqkv, __half* __restrict__ WqT,
    const float* __restrict__ wo, __half* __restrict__ WoT)
{
    __shared__ float t[32][33];
    const int bid = blockIdx.x;
    const int tid = threadIdx.x;

    if (bid < NB_A) {
        int i = bid * 256 + tid;
        float4 v = *(const float4*)(x + (size_t)i * 4);
        float vv[4] = {v.x, v.y, v.z, v.w};
        __half h[4], l[4];
#pragma unroll
        for (int j = 0; j < 4; j++) {
            h[j] = __float2half_rn(vv[j]);
            l[j] = __float2half_rn(vv[j] - __half2float(h[j]));
        }
        *(uint2*)(Xh + (size_t)i * 4) = *(uint2*)h;
        *(uint2*)(Xl + (size_t)i * 4) = *(uint2*)l;
        return;
    }

    const float* W;
    __half* T;
    int N, tb;
    if (bid < NB_A + NB_B) {
        W = wqkv; T = WqT; N = QKVN; tb = bid - NB_A;
    } else {
        W = wo; T = WoT; N = DIM_; tb = bid - NB_A - NB_B;
    }
    const int ntiles = N / 32;
    const int bx = tb % ntiles, by = tb / ntiles;
    const int k0 = by * 32, n0 = bx * 32;
    const int tx = tid & 31, ty = tid >> 5;
#pragma unroll
    for (int i = 0; i < 32; i += 8)
        t[ty + i][tx] = W[(size_t)(k0 + ty + i) * N + n0 + tx];
    __syncthreads();
#pragma unroll
    for (int i = 0; i < 32; i += 8) {
        float v = t[tx][ty + i];
        T[(size_t)(n0 + ty + i) * KDIM + k0 + tx] = __float2half_rn(v);
    }
}

// ============================================================================
// Flash attention: 128-row q tiles, 8 warps (256 thr). QK 1-term, PV 1-term.
// kv tiles of 64, double-buffered. Bit-identical math to the 64-row version
// (extra fully-masked tiles contribute exact zeros).
// ============================================================================
#define FSTR 144
#define FTILE (64 * FSTR)        // 9216
#define FSTAGE (2 * FTILE)       // Kh, Vh: 18432
#define FSMEM (2 * FSTAGE)       // 36864

__global__ __launch_bounds__(256) void flash_tc_kernel(
    const __half* __restrict__ Qh,
    const __half* __restrict__ Kh,
    const __half* __restrict__ Vh,
    __half* __restrict__ Oh)
{
    extern __shared__ char smem[];
    const uint32_t sb = smem_u32(smem);
    const int tid  = threadIdx.x;
    const int wid  = tid >> 5;           // 0..7
    const int lane = tid & 31;
    const int qtile = blockIdx.x;        // 0..15
    const int h     = blockIdx.y;
    const int b     = blockIdx.z;
    const int kvh   = h >> 2;
    const int q0    = qtile * 128;
    const int wm    = wid * 16;          // 0..112

    const __half* qhp = Qh + ((size_t)(b * NH_ + h) * S_ + q0) * HD_;
    const __half* khp = Kh + ((size_t)(b * NKV_ + kvh) * S_) * HD_;
    const __half* vhp = Vh + ((size_t)(b * NKV_ + kvh) * S_) * HD_;

    // stage Q (128 rows x 64 halves): 1024 slots / 256 threads = 4 each
#pragma unroll
    for (int i = 0; i < 4; i++) {
        int slot = tid + 256 * i;
        int r = slot >> 3, sg = slot & 7;
        cp_async16(sb + r * FSTR + sg * 16, qhp + (size_t)r * HD_ + sg * 8);
    }
    cp_commit();
    cp_wait0();
    __syncthreads();

    const uint32_t aoff = (uint32_t)((lane & 15) * FSTR + (lane >> 4) * 16);
    const uint32_t boff = (uint32_t)(((lane & 7) + ((lane >> 4) * 8)) * FSTR
                                     + (((lane >> 3) & 1) * 16));
    const uint32_t voff = (uint32_t)(((lane & 7) + (((lane >> 3) & 1) * 8)) * FSTR
                                     + ((lane >> 4) * 16));

    uint32_t qf[4][4];
#pragma unroll
    for (int ks = 0; ks < 4; ks++) {
        uint32_t rowb = (uint32_t)(wm * FSTR + ks * 32);
        ldmatrix_x4(qf[ks][0], qf[ks][1], qf[ks][2], qf[ks][3], sb + rowb + aoff);
    }
    __syncthreads();

    auto load_kv = [&](int st, int j) {
        uint32_t base = sb + st * FSTAGE;
        size_t g0 = (size_t)(j * 64) * HD_;
        // K and V tiles: 512 slots each / 256 threads = 2 each
#pragma unroll
        for (int i = 0; i < 2; i++) {
            int slot = tid + 256 * i;
            int r = slot >> 3, sg = slot & 7;
            uint32_t so = r * FSTR + sg * 16;
            size_t go = g0 + (size_t)r * HD_ + sg * 8;
            cp_async16(base + so, khp + go);
            cp_async16(base + FTILE + so, vhp + go);
        }
        cp_commit();
    };
    load_kv(0, 0);

    float m0 = -1e30f, m1 = -1e30f, l0 = 0.f, l1 = 0.f;
    float o[8][4];
#pragma unroll
    for (int nj = 0; nj < 8; nj++)
#pragma unroll
        for (int e = 0; e < 4; e++) o[nj][e] = 0.f;

    const int r0 = lane >> 2;
    const int tig = lane & 3;
    const int qg0 = q0 + wm + r0;
    const int qg1 = qg0 + 8;

    const int niters = 2 * qtile + 2;
    for (int j = 0; j < niters; j++) {
        cp_wait0();
        __syncthreads();
        if (j + 1 < niters) load_kv((j + 1) & 1, j + 1);

        uint32_t base = sb + (j & 1) * FSTAGE;
        uint32_t bKh = base;
        uint32_t bVh = base + FTILE;

        float c[8][4];
#pragma unroll
        for (int nj = 0; nj < 8; nj++)
#pragma unroll
            for (int e = 0; e < 4; e++) c[nj][e] = 0.f;

#pragma unroll
        for (int ks = 0; ks < 4; ks++) {
            uint32_t kf[4][4];
#pragma unroll
            for (int njp = 0; njp < 4; njp++) {
                uint32_t off = (uint32_t)(njp * 16 * FSTR + ks * 32) + boff;
                ldmatrix_x4(kf[njp][0], kf[njp][1], kf[njp][2], kf[njp][3], bKh + off);
            }
#pragma unroll
            for (int njp = 0; njp < 4; njp++) {
                mma_fp16(c[2 * njp],     qf[ks][0], qf[ks][1], qf[ks][2], qf[ks][3], kf[njp][0], kf[njp][1]);
                mma_fp16(c[2 * njp + 1], qf[ks][0], qf[ks][1], qf[ks][2], qf[ks][3], kf[njp][2], kf[njp][3]);
            }
        }

        const bool diag = (j >= 2 * qtile);   // only last two tiles can cross the diagonal
        float tm0 = -1e30f, tm1 = -1e30f;
#pragma unroll
        for (int nj = 0; nj < 8; nj++) {
            int colb = j * 64 + nj * 8 + 2 * tig;
#pragma unroll
            for (int e = 0; e < 4; e++) {
                float sv = c[nj][e] * 0.125f;
                if (diag) {
                    int colg = colb + (e & 1);
                    int rowg = (e < 2) ? qg0 : qg1;
                    if (colg > rowg) sv = -1e30f;
                }
                c[nj][e] = sv;
            }
            tm0 = fmaxf(tm0, fmaxf(c[nj][0], c[nj][1]));
            tm1 = fmaxf(tm1, fmaxf(c[nj][2], c[nj][3]));
        }
        tm0 = fmaxf(tm0, __shfl_xor_sync(0xffffffffu, tm0, 1));
        tm0 = fmaxf(tm0, __shfl_xor_sync(0xffffffffu, tm0, 2));
        tm1 = fmaxf(tm1, __shfl_xor_sync(0xffffffffu, tm1, 1));
        tm1 = fmaxf(tm1, __shfl_xor_sync(0xffffffffu, tm1, 2));

        float mn0 = fmaxf(m0, tm0), mn1 = fmaxf(m1, tm1);
        float sc0 = __expf(m0 - mn0), sc1 = __expf(m1 - mn1);
        m0 = mn0; m1 = mn1;

        float sum0 = 0.f, sum1 = 0.f;
#pragma unroll
        for (int nj = 0; nj < 8; nj++) {
            c[nj][0] = __expf(c[nj][0] - mn0);
            c[nj][1] = __expf(c[nj][1] - mn0);
            c[nj][2] = __expf(c[nj][2] - mn1);
            c[nj][3] = __expf(c[nj][3] - mn1);
            sum0 += c[nj][0] + c[nj][1];
            sum1 += c[nj][2] + c[nj][3];
        }
        sum0 += __shfl_xor_sync(0xffffffffu, sum0, 1);
        sum0 += __shfl_xor_sync(0xffffffffu, sum0, 2);
        sum1 += __shfl_xor_sync(0xffffffffu, sum1, 1);
        sum1 += __shfl_xor_sync(0xffffffffu, sum1, 2);
        l0 = l0 * sc0 + sum0;
        l1 = l1 * sc1 + sum1;

#pragma unroll
        for (int nj = 0; nj < 8; nj++) {
            o[nj][0] *= sc0; o[nj][1] *= sc0;
            o[nj][2] *= sc1; o[nj][3] *= sc1;
        }

#pragma unroll
        for (int ksv = 0; ksv < 4; ksv++) {
            uint32_t ap[4];
            ap[0] = pack_h2(c[2 * ksv][0], c[2 * ksv][1]);
            ap[1] = pack_h2(c[2 * ksv][2], c[2 * ksv][3]);
            ap[2] = pack_h2(c[2 * ksv + 1][0], c[2 * ksv + 1][1]);
            ap[3] = pack_h2(c[2 * ksv + 1][2], c[2 * ksv + 1][3]);
#pragma unroll
            for (int njp = 0; njp < 4; njp++) {
                uint32_t off = (uint32_t)(ksv * 16 * FSTR + njp * 32) + voff;
                uint32_t v0, v1, v2, v3;
                ldmatrix_x4_trans(v0, v1, v2, v3, bVh + off);
                mma_fp16(o[2 * njp],     ap[0], ap[1], ap[2], ap[3], v0, v1);
                mma_fp16(o[2 * njp + 1], ap[0], ap[1], ap[2], ap[3], v2, v3);
            }
        }
    }

    float inv0 = 1.f / l0, inv1 = 1.f / l1;
    size_t gr0 = (size_t)(b * S_ + q0 + wm + r0) * DIM_ + h * HD_ + 2 * tig;
    size_t gr1 = gr0 + (size_t)8 * DIM_;
#pragma unroll
    for (int nj = 0; nj < 8; nj++) {
        *(uint32_t*)(Oh + gr0 + nj * 8) = pack_h2(o[nj][0] * inv0, o[nj][1] * inv0);
        *(uint32_t*)(Oh + gr1 + nj * 8) = pack_h2(o[nj][2] * inv1, o[nj][3] * inv1);
    }
}

// ============================================================================
// launch
// ============================================================================
extern "C" void kernel_launch(void* const* d_in, const int* in_sizes, int n_in,
                              void* d_out, int out_size)
{
    const float* x    = (const float*)d_in[0];
    const float* fc   = (const float*)d_in[1];
    const float* wqkv = (const float*)d_in[2];
    const float* wo   = (const float*)d_in[3];
    float* out        = (float*)d_out;

    void *xh_p, *xl_p, *wqh_p, *woh_p, *ah_p;
    void *qh_p, *kh_p, *vh_p;
    cudaGetSymbolAddress(&xh_p, g_x_hi);
    cudaGetSymbolAddress(&xl_p, g_x_lo);
    cudaGetSymbolAddress(&wqh_p, g_wqkvT_hi);
    cudaGetSymbolAddress(&woh_p, g_woT_hi);
    cudaGetSymbolAddress(&ah_p, g_att_hi);
    cudaGetSymbolAddress(&qh_p, g_q_hi);
    cudaGetSymbolAddress(&kh_p, g_k_hi);
    cudaGetSymbolAddress(&vh_p, g_v_hi);

    cudaFuncSetAttribute(tc_gemm2_kernel, cudaFuncAttributeMaxDynamicSharedMemorySize,
                         G2SMEM);
    cudaFuncSetAttribute(tc_gemm1_kernel, cudaFuncAttributeMaxDynamicSharedMemorySize,
                         G1SMEM);
    cudaFuncSetAttribute(flash_tc_kernel, cudaFuncAttributeMaxDynamicSharedMemorySize,
                         FSMEM);

    // 1) all conversions in one launch
    conv_fused_kernel<<<NB_TOTAL, 256>>>(
        x, (__half*)xh_p, (__half*)xl_p,
        wqkv, (__half*)wqh_p,
        wo, (__half*)woh_p);

    // 2) qkv projection (2-term) + fused rope epilogue -> Q/K/V fp16
    tc_gemm2_kernel<<<dim3(QKVN / GBN, M_ / GBM), 128, G2SMEM>>>(
        (const __half*)xh_p, (const __half*)xl_p,
        (const __half*)wqh_p, fc,
        (__half*)qh_p, (__half*)kh_p, (__half*)vh_p,
        QKVN, KDIM);

    // 3) flash attention (128-row q tiles) -> att fp16
    flash_tc_kernel<<<dim3(S_ / 128, NH_, B_), 256, FSMEM>>>(
        (const __half*)qh_p, (const __half*)kh_p, (const __half*)vh_p,
        (__half*)ah_p);

    // 4) out = att @ wo (1-term fp16)
    tc_gemm1_kernel<<<dim3(DIM_ / GBN, M_ / GBM), 128, G1SMEM>>>(
        (const __half*)ah_p, (const __half*)woh_p, out, DIM_, KDIM);
}

// round 15
// speedup vs baseline: 1.0265x; 1.0265x over previous
#include <cuda_runtime.h>
#include <cuda_fp16.h>
#include <cstdint>

// ---------------- problem constants ----------------
#define B_   2
#define S_   2048
#define DIM_ 2048
#define NH_  32
#define NKV_ 8
#define HD_  64
#define QKVN 3072
#define M_   (B_ * S_)
#define KDIM 2048

// ---------------- scratch (fp16) ----------------
__device__ __half g_x_hi[(size_t)M_ * DIM_];
__device__ __half g_x_lo[(size_t)M_ * DIM_];
__device__ __half g_wqkvT_hi[(size_t)QKVN * DIM_];
__device__ __half g_woT_hi[(size_t)DIM_ * DIM_];
__device__ __half g_att_hi[(size_t)M_ * DIM_];
__device__ __half g_q_hi[(size_t)B_ * NH_ * S_ * HD_];
__device__ __half g_k_hi[(size_t)B_ * NKV_ * S_ * HD_];
__device__ __half g_v_hi[(size_t)B_ * NKV_ * S_ * HD_];

// ============================================================================
// helpers (sm_80-compatible only)
// ============================================================================
__device__ __forceinline__ uint32_t smem_u32(const void* p) {
    uint32_t a;
    asm("{ .reg .u64 t; cvta.to.shared.u64 t, %1; cvt.u32.u64 %0, t; }"
        : "=r"(a) : "l"(p));
    return a;
}
__device__ __forceinline__ void cp_async16(uint32_t s, const void* g) {
    asm volatile("cp.async.cg.shared.global [%0], [%1], 16;" :: "r"(s), "l"(g));
}
__device__ __forceinline__ void cp_commit() {
    asm volatile("cp.async.commit_group;" ::: "memory");
}
__device__ __forceinline__ void cp_wait0() {
    asm volatile("cp.async.wait_group 0;" ::: "memory");
}
__device__ __forceinline__ void ldmatrix_x4(uint32_t& r0, uint32_t& r1,
                                            uint32_t& r2, uint32_t& r3, uint32_t a) {
    asm volatile("ldmatrix.sync.aligned.m8n8.x4.shared.b16 {%0,%1,%2,%3}, [%4];"
                 : "=r"(r0), "=r"(r1), "=r"(r2), "=r"(r3) : "r"(a));
}
__device__ __forceinline__ void ldmatrix_x4_trans(uint32_t& r0, uint32_t& r1,
                                                  uint32_t& r2, uint32_t& r3, uint32_t a) {
    asm volatile("ldmatrix.sync.aligned.m8n8.x4.trans.shared.b16 {%0,%1,%2,%3}, [%4];"
                 : "=r"(r0), "=r"(r1), "=r"(r2), "=r"(r3) : "r"(a));
}
__device__ __forceinline__ void mma_fp16(float* c, uint32_t a0, uint32_t a1,
                                         uint32_t a2, uint32_t a3,
                                         uint32_t b0, uint32_t b1) {
    asm volatile(
        "mma.sync.aligned.m16n8k16.row.col.f32.f16.f16.f32 "
        "{%0,%1,%2,%3}, {%4,%5,%6,%7}, {%8,%9}, {%0,%1,%2,%3};"
        : "+f"(c[0]), "+f"(c[1]), "+f"(c[2]), "+f"(c[3])
        : "r"(a0), "r"(a1), "r"(a2), "r"(a3), "r"(b0), "r"(b1));
}
__device__ __forceinline__ uint32_t pack_h2(float a, float b) {
    __half2 t = __floats2half2_rn(a, b);
    return *(uint32_t*)&t;
}

// ============================================================================
// GEMM tiling: 64 M-rows per CTA, BK=64 (32 iterations, 4 k-steps each)
// ============================================================================
#define GBM 64
#define GBN 128
#define GBK 64
#define GSTRIDE 144                   // 64 halves (128B) + 16B pad
#define GTILE_A (GBM * GSTRIDE)       // 9216 B
#define GTILE_B (GBN * GSTRIDE)       // 18432 B

// ---- tc_gemm2: C = (Ah+Al) @ Bh^T, fused rope + Q/K/V epilogue ----
#define G2STAGE (2 * GTILE_A + GTILE_B)   // 36864
#define G2SMEM (2 * G2STAGE)              // 73728

__global__ __launch_bounds__(128) void tc_gemm2_kernel(
    const __half* __restrict__ Ah, const __half* __restrict__ Al,
    const __half* __restrict__ Bh,
    const float* __restrict__ fc,
    __half* __restrict__ Qh,
    __half* __restrict__ Kh,
    __half* __restrict__ Vh,
    int N, int K)
{
    extern __shared__ char smem[];
    const uint32_t sb = smem_u32(smem);
    const int tid = threadIdx.x;
    const int wid = tid >> 5;
    const int lane = tid & 31;
    const int mb = blockIdx.y * GBM;
    const int nb = blockIdx.x * GBN;
    const int wm = (wid >> 1) * 32;    // warp tile 32x64
    const int wn = (wid & 1) * 64;

    auto load_stage = [&](int stage, int k0) {
        uint32_t base = sb + stage * G2STAGE;
        uint32_t sAh = base, sAl = base + GTILE_A, sB = base + 2 * GTILE_A;
#pragma unroll
        for (int i = 0; i < 4; i++) {
            int slot = i * 128 + tid;
            int r = slot >> 3, sg = slot & 7;
            cp_async16(sAh + r * GSTRIDE + sg * 16, Ah + (size_t)(mb + r) * K + k0 + sg * 8);
            cp_async16(sAl + r * GSTRIDE + sg * 16, Al + (size_t)(mb + r) * K + k0 + sg * 8);
        }
#pragma unroll
        for (int i = 0; i < 8; i++) {
            int slot = i * 128 + tid;
            int r = slot >> 3, sg = slot & 7;
            cp_async16(sB + r * GSTRIDE + sg * 16, Bh + (size_t)(nb + r) * K + k0 + sg * 8);
        }
        cp_commit();
    };

    float acc[2][8][4];
#pragma unroll
    for (int i = 0; i < 2; i++)
#pragma unroll
        for (int j = 0; j < 8; j++)
#pragma unroll
            for (int e = 0; e < 4; e++) acc[i][j][e] = 0.f;

    const uint32_t aoff = (uint32_t)((lane & 15) * GSTRIDE + (lane >> 4) * 16);
    const uint32_t boff = (uint32_t)(((lane & 7) + ((lane >> 4) * 8)) * GSTRIDE
                                     + (((lane >> 3) & 1) * 16));

    load_stage(0, 0);
    const int niter = K / GBK;
    for (int it = 0; it < niter; it++) {
        cp_wait0();
        __syncthreads();
        if (it + 1 < niter) load_stage((it + 1) & 1, (it + 1) * GBK);

        uint32_t base = sb + (it & 1) * G2STAGE;
        uint32_t bAh = base, bAl = base + GTILE_A, bB = base + 2 * GTILE_A;

#pragma unroll
        for (int ks = 0; ks < 4; ks++) {
            uint32_t kb = (uint32_t)(ks * 32);
            uint32_t ah[2][4], al[2][4];
#pragma unroll
            for (int mi = 0; mi < 2; mi++) {
                uint32_t rowb = (uint32_t)((wm + mi * 16) * GSTRIDE) + kb;
                ldmatrix_x4(ah[mi][0], ah[mi][1], ah[mi][2], ah[mi][3], bAh + rowb + aoff);
                ldmatrix_x4(al[mi][0], al[mi][1], al[mi][2], al[mi][3], bAl + rowb + aoff);
            }
            uint32_t bf[8][2];
#pragma unroll
            for (int nj = 0; nj < 4; nj++) {
                uint32_t rowb = (uint32_t)((wn + nj * 16) * GSTRIDE) + kb;
                uint32_t t0, t1, t2, t3;
                ldmatrix_x4(t0, t1, t2, t3, bB + rowb + boff);
                bf[nj * 2][0] = t0; bf[nj * 2][1] = t1;
                bf[nj * 2 + 1][0] = t2; bf[nj * 2 + 1][1] = t3;
            }
#pragma unroll
            for (int mi = 0; mi < 2; mi++)
#pragma unroll
                for (int nj = 0; nj < 8; nj++) {
                    mma_fp16(acc[mi][nj], ah[mi][0], ah[mi][1], ah[mi][2], ah[mi][3],
                             bf[nj][0], bf[nj][1]);
                    mma_fp16(acc[mi][nj], al[mi][0], al[mi][1], al[mi][2], al[mi][3],
                             bf[nj][0], bf[nj][1]);
                }
        }
        // trailing __syncthreads removed: next-iter top barrier provides ordering
    }

    const int g = lane >> 2, c = lane & 3;
#pragma unroll
    for (int mi = 0; mi < 2; mi++) {
#pragma unroll
        for (int nj = 0; nj < 8; nj++) {
            const int col = nb + wn + nj * 8 + 2 * c;
#pragma unroll
            for (int rr = 0; rr < 2; rr++) {
                const int row = mb + wm + mi * 16 + g + rr * 8;
                float v0 = acc[mi][nj][rr * 2 + 0];
                float v1 = acc[mi][nj][rr * 2 + 1];
                const int b = row >> 11, s = row & (S_ - 1);
                const int d = col & 63;
                if (col < DIM_ + NKV_ * HD_) {
                    float2 f = *(const float2*)(fc + (size_t)s * HD_ + d);
                    float rx = v0 * f.x - v1 * f.y;
                    float ry = v1 * f.x + v0 * f.y;
                    v0 = rx; v1 = ry;
                }
                if (col < DIM_) {
                    int h = col >> 6;
                    size_t o = ((size_t)(b * NH_ + h) * S_ + s) * HD_ + d;
                    *(uint32_t*)(Qh + o) = pack_h2(v0, v1);
                } else if (col < DIM_ + NKV_ * HD_) {
                    int kvh = (col - DIM_) >> 6;
                    size_t o = ((size_t)(b * NKV_ + kvh) * S_ + s) * HD_ + d;
                    *(uint32_t*)(Kh + o) = pack_h2(v0, v1);
                } else {
                    int kvh = (col - DIM_ - NKV_ * HD_) >> 6;
                    size_t o = ((size_t)(b * NKV_ + kvh) * S_ + s) * HD_ + d;
                    *(uint32_t*)(Vh + o) = pack_h2(v0, v1);
                }
            }
        }
    }
}

// ---- tc_gemm1: single-term fp16 GEMM (out = att @ woT^T), BK=64 ----
#define G1STAGE (GTILE_A + GTILE_B)   // 27648
#define G1SMEM (2 * G1STAGE)          // 55296

__global__ __launch_bounds__(128) void tc_gemm1_kernel(
    const __half* __restrict__ A, const __half* __restrict__ B,
    float* __restrict__ C, int N, int K)
{
    extern __shared__ char smem[];
    const uint32_t sb = smem_u32(smem);
    const int tid = threadIdx.x;
    const int wid = tid >> 5;
    const int lane = tid & 31;
    const int mb = blockIdx.y * GBM;
    const int nb = blockIdx.x * GBN;
    const int wm = (wid >> 1) * 32;
    const int wn = (wid & 1) * 64;

    auto load_stage = [&](int stage, int k0) {
        uint32_t base = sb + stage * G1STAGE;
        uint32_t sA = base, sB = base + GTILE_A;
#pragma unroll
        for (int i = 0; i < 4; i++) {
            int slot = i * 128 + tid;
            int r = slot >> 3, sg = slot & 7;
            cp_async16(sA + r * GSTRIDE + sg * 16, A + (size_t)(mb + r) * K + k0 + sg * 8);
        }
#pragma unroll
        for (int i = 0; i < 8; i++) {
            int slot = i * 128 + tid;
            int r = slot >> 3, sg = slot & 7;
            cp_async16(sB + r * GSTRIDE + sg * 16, B + (size_t)(nb + r) * K + k0 + sg * 8);
        }
        cp_commit();
    };

    float acc[2][8][4];
#pragma unroll
    for (int i = 0; i < 2; i++)
#pragma unroll
        for (int j = 0; j < 8; j++)
#pragma unroll
            for (int e = 0; e < 4; e++) acc[i][j][e] = 0.f;

    const uint32_t aoff = (uint32_t)((lane & 15) * GSTRIDE + (lane >> 4) * 16);
    const uint32_t boff = (uint32_t)(((lane & 7) + ((lane >> 4) * 8)) * GSTRIDE
                                     + (((lane >> 3) & 1) * 16));

    load_stage(0, 0);
    const int niter = K / GBK;
    for (int it = 0; it < niter; it++) {
        cp_wait0();
        __syncthreads();
        if (it + 1 < niter) load_stage((it + 1) & 1, (it + 1) * GBK);

        uint32_t base = sb + (it & 1) * G1STAGE;
        uint32_t bA = base, bB = base + GTILE_A;

#pragma unroll
        for (int ks = 0; ks < 4; ks++) {
            uint32_t kb = (uint32_t)(ks * 32);
            uint32_t af[2][4];
#pragma unroll
            for (int mi = 0; mi < 2; mi++) {
                uint32_t rowb = (uint32_t)((wm + mi * 16) * GSTRIDE) + kb;
                ldmatrix_x4(af[mi][0], af[mi][1], af[mi][2], af[mi][3], bA + rowb + aoff);
            }
            uint32_t bf[8][2];
#pragma unroll
            for (int nj = 0; nj < 4; nj++) {
                uint32_t rowb = (uint32_t)((wn + nj * 16) * GSTRIDE) + kb;
                uint32_t t0, t1, t2, t3;
                ldmatrix_x4(t0, t1, t2, t3, bB + rowb + boff);
                bf[nj * 2][0] = t0; bf[nj * 2][1] = t1;
                bf[nj * 2 + 1][0] = t2; bf[nj * 2 + 1][1] = t3;
            }
#pragma unroll
            for (int mi = 0; mi < 2; mi++)
#pragma unroll
                for (int nj = 0; nj < 8; nj++)
                    mma_fp16(acc[mi][nj], af[mi][0], af[mi][1], af[mi][2], af[mi][3],
                             bf[nj][0], bf[nj][1]);
        }
        // trailing __syncthreads removed
    }

    const int g = lane >> 2, c = lane & 3;
#pragma unroll
    for (int mi = 0; mi < 2; mi++) {
#pragma unroll
        for (int nj = 0; nj < 8; nj++) {
            float* cp0 = C + (size_t)(mb + wm + mi * 16 + g) * N + nb + wn + nj * 8 + 2 * c;
            float* cp1 = cp0 + (size_t)8 * N;
            *(float2*)cp0 = make_float2(acc[mi][nj][0], acc[mi][nj][1]);
            *(float2*)cp1 = make_float2(acc[mi][nj][2], acc[mi][nj][3]);
        }
    }
}

// ============================================================================
// Fused conversion kernel (unchanged)
// ============================================================================
#define NB_A (M_ * DIM_ / 4 / 256)            // 8192
#define NB_B ((KDIM / 32) * (QKVN / 32))      // 6144
#define NB_C ((KDIM / 32) * (DIM_ / 32))      // 4096
#define NB_TOTAL (NB_A + NB_B + NB_C)         // 18432

__global__ __launch_bounds__(256) void conv_fused_kernel(
    const float* __restrict__ x, __half* __restrict__ Xh, __half* __restrict__ Xl,
    const float* __restrict__ wqkv, __half* __restrict__ WqT,
    const float* __restrict__ wo, __half* __restrict__ WoT)
{
    __shared__ float t[32][33];
    const int bid = blockIdx.x;
    const int tid = threadIdx.x;

    if (bid < NB_A) {
        int i = bid * 256 + tid;
        float4 v = *(const float4*)(x + (size_t)i * 4);
        float vv[4] = {v.x, v.y, v.z, v.w};
        __half h[4], l[4];
#pragma unroll
        for (int j = 0; j < 4; j++) {
            h[j] = __float2half_rn(vv[j]);
            l[j] = __float2half_rn(vv[j] - __half2float(h[j]));
        }
        *(uint2*)(Xh + (size_t)i * 4) = *(uint2*)h;
        *(uint2*)(Xl + (size_t)i * 4) = *(uint2*)l;
        return;
    }

    const float* W;
    __half* T;
    int N, tb;
    if (bid < NB_A + NB_B) {
        W = wqkv; T = WqT; N = QKVN; tb = bid - NB_A;
    } else {
        W = wo; T = WoT; N = DIM_; tb = bid - NB_A - NB_B;
    }
    const int ntiles = N / 32;
    const int bx = tb % ntiles, by = tb / ntiles;
    const int k0 = by * 32, n0 = bx * 32;
    const int tx = tid & 31, ty = tid >> 5;
#pragma unroll
    for (int i = 0; i < 32; i += 8)
        t[ty + i][tx] = W[(size_t)(k0 + ty + i) * N + n0 + tx];
    __syncthreads();
#pragma unroll
    for (int i = 0; i < 32; i += 8) {
        float v = t[tx][ty + i];
        T[(size_t)(n0 + ty + i) * KDIM + k0 + tx] = __float2half_rn(v);
    }
}

// ============================================================================
// Flash attention (R13 version: 64-row q tiles, 128 threads, double buffer)
// ============================================================================
#define FSTR 144
#define FTILE (64 * FSTR)
#define FSTAGE (2 * FTILE)       // Kh, Vh
#define FSMEM (2 * FSTAGE)

__global__ __launch_bounds__(128) void flash_tc_kernel(
    const __half* __restrict__ Qh,
    const __half* __restrict__ Kh,
    const __half* __restrict__ Vh,
    __half* __restrict__ Oh)
{
    extern __shared__ char smem[];
    const uint32_t sb = smem_u32(smem);
    const int tid  = threadIdx.x;
    const int wid  = tid >> 5;
    const int lane = tid & 31;
    const int qtile = blockIdx.x;
    const int h     = blockIdx.y;
    const int b     = blockIdx.z;
    const int kvh   = h >> 2;
    const int q0    = qtile * 64;
    const int wm    = wid * 16;

    const __half* qhp = Qh + ((size_t)(b * NH_ + h) * S_ + q0) * HD_;
    const __half* khp = Kh + ((size_t)(b * NKV_ + kvh) * S_) * HD_;
    const __half* vhp = Vh + ((size_t)(b * NKV_ + kvh) * S_) * HD_;

    const int lr[4] = {(tid) >> 3, (tid + 128) >> 3, (tid + 256) >> 3, (tid + 384) >> 3};
    const int ls = tid & 7;

    // stage Q, build fragments
#pragma unroll
    for (int i = 0; i < 4; i++)
        cp_async16(sb + lr[i] * FSTR + ls * 16, qhp + (size_t)lr[i] * HD_ + ls * 8);
    cp_commit();
    cp_wait0();
    __syncthreads();

    const uint32_t aoff = (uint32_t)((lane & 15) * FSTR + (lane >> 4) * 16);
    const uint32_t boff = (uint32_t)(((lane & 7) + ((lane >> 4) * 8)) * FSTR
                                     + (((lane >> 3) & 1) * 16));
    const uint32_t voff = (uint32_t)(((lane & 7) + (((lane >> 3) & 1) * 8)) * FSTR
                                     + ((lane >> 4) * 16));

    uint32_t qf[4][4];
#pragma unroll
    for (int ks = 0; ks < 4; ks++) {
        uint32_t rowb = (uint32_t)(wm * FSTR + ks * 32);
        ldmatrix_x4(qf[ks][0], qf[ks][1], qf[ks][2], qf[ks][3], sb + rowb + aoff);
    }
    __syncthreads();

    auto load_kv = [&](int st, int j) {
        uint32_t base = sb + st * FSTAGE;
        size_t g0 = (size_t)(j * 64) * HD_;
#pragma unroll
        for (int i = 0; i < 4; i++) {
            uint32_t so = lr[i] * FSTR + ls * 16;
            size_t go = g0 + (size_t)lr[i] * HD_ + ls * 8;
            cp_async16(base + so, khp + go);
            cp_async16(base + FTILE + so, vhp + go);
        }
        cp_commit();
    };
    load_kv(0, 0);

    float m0 = -1e30f, m1 = -1e30f, l0 = 0.f, l1 = 0.f;
    float o[8][4];
#pragma unroll
    for (int nj = 0; nj < 8; nj++)
#pragma unroll
        for (int e = 0; e < 4; e++) o[nj][e] = 0.f;

    const int r0 = lane >> 2;
    const int tig = lane & 3;
    const int qg0 = q0 + wm + r0;
    const int qg1 = qg0 + 8;

    for (int j = 0; j <= qtile; j++) {
        cp_wait0();
        __syncthreads();
        if (j < qtile) load_kv((j + 1) & 1, j + 1);

        uint32_t base = sb + (j & 1) * FSTAGE;
        uint32_t bKh = base;
        uint32_t bVh = base + FTILE;

        float c[8][4];
#pragma unroll
        for (int nj = 0; nj < 8; nj++)
#pragma unroll
            for (int e = 0; e < 4; e++) c[nj][e] = 0.f;

#pragma unroll
        for (int ks = 0; ks < 4; ks++) {
            uint32_t kf[4][4];
#pragma unroll
            for (int njp = 0; njp < 4; njp++) {
                uint32_t off = (uint32_t)(njp * 16 * FSTR + ks * 32) + boff;
                ldmatrix_x4(kf[njp][0], kf[njp][1], kf[njp][2], kf[njp][3], bKh + off);
            }
#pragma unroll
            for (int njp = 0; njp < 4; njp++) {
                mma_fp16(c[2 * njp],     qf[ks][0], qf[ks][1], qf[ks][2], qf[ks][3], kf[njp][0], kf[njp][1]);
                mma_fp16(c[2 * njp + 1], qf[ks][0], qf[ks][1], qf[ks][2], qf[ks][3], kf[njp][2], kf[njp][3]);
            }
        }

        const bool diag = (j == qtile);
        float tm0 = -1e30f, tm1 = -1e30f;
#pragma unroll
        for (int nj = 0; nj < 8; nj++) {
            int colb = j * 64 + nj * 8 + 2 * tig;
#pragma unroll
            for (int e = 0; e < 4; e++) {
                float sv = c[nj][e] * 0.125f;
                if (diag) {
                    int colg = colb + (e & 1);
                    int rowg = (e < 2) ? qg0 : qg1;
                    if (colg > rowg) sv = -1e30f;
                }
                c[nj][e] = sv;
            }
            tm0 = fmaxf(tm0, fmaxf(c[nj][0], c[nj][1]));
            tm1 = fmaxf(tm1, fmaxf(c[nj][2], c[nj][3]));
        }
        tm0 = fmaxf(tm0, __shfl_xor_sync(0xffffffffu, tm0, 1));
        tm0 = fmaxf(tm0, __shfl_xor_sync(0xffffffffu, tm0, 2));
        tm1 = fmaxf(tm1, __shfl_xor_sync(0xffffffffu, tm1, 1));
        tm1 = fmaxf(tm1, __shfl_xor_sync(0xffffffffu, tm1, 2));

        float mn0 = fmaxf(m0, tm0), mn1 = fmaxf(m1, tm1);
        float sc0 = __expf(m0 - mn0), sc1 = __expf(m1 - mn1);
        m0 = mn0; m1 = mn1;

        float sum0 = 0.f, sum1 = 0.f;
#pragma unroll
        for (int nj = 0; nj < 8; nj++) {
            c[nj][0] = __expf(c[nj][0] - mn0);
            c[nj][1] = __expf(c[nj][1] - mn0);
            c[nj][2] = __expf(c[nj][2] - mn1);
            c[nj][3] = __expf(c[nj][3] - mn1);
            sum0 += c[nj][0] + c[nj][1];
            sum1 += c[nj][2] + c[nj][3];
        }
        sum0 += __shfl_xor_sync(0xffffffffu, sum0, 1);
        sum0 += __shfl_xor_sync(0xffffffffu, sum0, 2);
        sum1 += __shfl_xor_sync(0xffffffffu, sum1, 1);
        sum1 += __shfl_xor_sync(0xffffffffu, sum1, 2);
        l0 = l0 * sc0 + sum0;
        l1 = l1 * sc1 + sum1;

#pragma unroll
        for (int nj = 0; nj < 8; nj++) {
            o[nj][0] *= sc0; o[nj][1] *= sc0;
            o[nj][2] *= sc1; o[nj][3] *= sc1;
        }

#pragma unroll
        for (int ksv = 0; ksv < 4; ksv++) {
            uint32_t ap[4];
            ap[0] = pack_h2(c[2 * ksv][0], c[2 * ksv][1]);
            ap[1] = pack_h2(c[2 * ksv][2], c[2 * ksv][3]);
            ap[2] = pack_h2(c[2 * ksv + 1][0], c[2 * ksv + 1][1]);
            ap[3] = pack_h2(c[2 * ksv + 1][2], c[2 * ksv + 1][3]);
#pragma unroll
            for (int njp = 0; njp < 4; njp++) {
                uint32_t off = (uint32_t)(ksv * 16 * FSTR + njp * 32) + voff;
                uint32_t v0, v1, v2, v3;
                ldmatrix_x4_trans(v0, v1, v2, v3, bVh + off);
                mma_fp16(o[2 * njp],     ap[0], ap[1], ap[2], ap[3], v0, v1);
                mma_fp16(o[2 * njp + 1], ap[0], ap[1], ap[2], ap[3], v2, v3);
            }
        }
    }

    float inv0 = 1.f / l0, inv1 = 1.f / l1;
    size_t gr0 = (size_t)(b * S_ + q0 + wm + r0) * DIM_ + h * HD_ + 2 * tig;
    size_t gr1 = gr0 + (size_t)8 * DIM_;
#pragma unroll
    for (int nj = 0; nj < 8; nj++) {
        *(uint32_t*)(Oh + gr0 + nj * 8) = pack_h2(o[nj][0] * inv0, o[nj][1] * inv0);
        *(uint32_t*)(Oh + gr1 + nj * 8) = pack_h2(o[nj][2] * inv1, o[nj][3] * inv1);
    }
}

// ============================================================================
// launch
// ============================================================================
extern "C" void kernel_launch(void* const* d_in, const int* in_sizes, int n_in,
                              void* d_out, int out_size)
{
    const float* x    = (const float*)d_in[0];
    const float* fc   = (const float*)d_in[1];
    const float* wqkv = (const float*)d_in[2];
    const float* wo   = (const float*)d_in[3];
    float* out        = (float*)d_out;

    void *xh_p, *xl_p, *wqh_p, *woh_p, *ah_p;
    void *qh_p, *kh_p, *vh_p;
    cudaGetSymbolAddress(&xh_p, g_x_hi);
    cudaGetSymbolAddress(&xl_p, g_x_lo);
    cudaGetSymbolAddress(&wqh_p, g_wqkvT_hi);
    cudaGetSymbolAddress(&woh_p, g_woT_hi);
    cudaGetSymbolAddress(&ah_p, g_att_hi);
    cudaGetSymbolAddress(&qh_p, g_q_hi);
    cudaGetSymbolAddress(&kh_p, g_k_hi);
    cudaGetSymbolAddress(&vh_p, g_v_hi);

    cudaFuncSetAttribute(tc_gemm2_kernel, cudaFuncAttributeMaxDynamicSharedMemorySize,
                         G2SMEM);
    cudaFuncSetAttribute(tc_gemm1_kernel, cudaFuncAttributeMaxDynamicSharedMemorySize,
                         G1SMEM);
    cudaFuncSetAttribute(flash_tc_kernel, cudaFuncAttributeMaxDynamicSharedMemorySize,
                         FSMEM);

    // 1) all conversions in one launch
    conv_fused_kernel<<<NB_TOTAL, 256>>>(
        x, (__half*)xh_p, (__half*)xl_p,
        wqkv, (__half*)wqh_p,
        wo, (__half*)woh_p);

    // 2) qkv projection (2-term) + fused rope epilogue -> Q/K/V fp16
    tc_gemm2_kernel<<<dim3(QKVN / GBN, M_ / GBM), 128, G2SMEM>>>(
        (const __half*)xh_p, (const __half*)xl_p,
        (const __half*)wqh_p, fc,
        (__half*)qh_p, (__half*)kh_p, (__half*)vh_p,
        QKVN, KDIM);

    // 3) flash attention (64-row q tiles) -> att fp16
    flash_tc_kernel<<<dim3(S_ / 64, NH_, B_), 128, FSMEM>>>(
        (const __half*)qh_p, (const __half*)kh_p, (const __half*)vh_p,
        (__half*)ah_p);

    // 4) out = att @ wo (1-term fp16)
    tc_gemm1_kernel<<<dim3(DIM_ / GBN, M_ / GBM), 128, G1SMEM>>>(
        (const __half*)ah_p, (const __half*)woh_p, out, DIM_, KDIM);
}